// round 16
// baseline (speedup 1.0000x reference)
#include <cuda_runtime.h>
#include <cuda_fp16.h>
#include <math.h>
#include <stdint.h>

#define HID 256
#define NH 4
#define NL 2
#define TOUT 12
#define MAXN 24000
#define MAXE 400000

// ---------------- scratch (static device globals; no allocation) ----------------
__device__ __half g_xl[MAXN * HID];
__device__ __half g_xr[MAXN * HID];
__device__ float g_elog[MAXE * NH];
__device__ int   g_deg[MAXN];
__device__ int   g_off[MAXN + 1];
__device__ int   g_cur[MAXN];
__device__ int   g_eidx[MAXE];
__device__ __half g_G0[(size_t)MAXN * 1024];
__device__ float g_c[MAXN * HID];
__device__ float g_prev[MAXN];
__device__ float g_up[1024];
__device__ float g_bsp[1024];

// fp16 activation buffers
__device__ __half g_s0[MAXN * HID];
__device__ __half g_hA[MAXN * HID];
__device__ __half g_hB[MAXN * HID];
__device__ __half g_cs[MAXN * HID];
// fp16 weights (single-term)
__device__ __half g_wg[4 * 256 * 256];
__device__ __half g_mb[256 * 256];
__device__ __half g_wih[1024 * 256];
__device__ __half g_whh[1024 * 256];

// ---------------- helpers ----------------
__device__ __forceinline__ uint32_t smem_u32(const void* p) {
    uint32_t a;
    asm("{ .reg .u64 t; cvta.to.shared.u64 t, %1; cvt.u32.u64 %0, t; }" : "=r"(a) : "l"(p));
    return a;
}
__device__ __forceinline__ uint32_t swz(uint32_t b) { return b ^ ((b >> 3) & 0x70); }
__device__ __forceinline__ float sigm(float x) { return 1.f / (1.f + expf(-x)); }

#define LDSM4(r, a) \
    asm volatile("ldmatrix.sync.aligned.m8n8.x4.shared.b16 {%0,%1,%2,%3}, [%4];" \
                 : "=r"((r)[0]), "=r"((r)[1]), "=r"((r)[2]), "=r"((r)[3]) : "r"(a))

// fp16-accumulate MMA (2x issue rate vs f32-acc on legacy HMMA pipe)
#define MMA_F16A(d, a, b0v, b1v) \
    asm volatile("mma.sync.aligned.m16n8k16.row.col.f16.f16.f16.f16 " \
                 "{%0,%1}, {%2,%3,%4,%5}, {%6,%7}, {%0,%1};" \
                 : "+r"((d)[0]), "+r"((d)[1]) \
                 : "r"((a)[0]), "r"((a)[1]), "r"((a)[2]), "r"((a)[3]), "r"(b0v), "r"(b1v))

// ---------------- HMMA GEMM: C[M,Nc] = A[M,256] @ W[Nc,256]^T ----------------
// fp16 operands; fp16 accumulation within each K=64 chunk, fp32 combine across chunks.
// Synchronous loader (R13-proven structure; NO cp.async, NO register prefetch, NO merge).
// 128x128 CTA tile, 256 threads: warp grid 4(m) x 2(n), warp tile 32x64.
#define SM_A  1024
#define SM_B  (1024 + 16384)
#define SC_P 129
#define SM_TOTAL (1024 + 128 * SC_P * 4)  // 67072 (mainloop needs 1024 + 32768)
enum { E_STOREH = 0, E_BIASH = 1, E_LSTM = 2 };

template <int EPI>
__global__ void __launch_bounds__(256, 2)
gemm_mma(const __half* __restrict__ A, const __half* __restrict__ B,
         int M, int ldc,
         const float* __restrict__ bias,
         __half* __restrict__ Oh,
         const __half* __restrict__ G0, const float* __restrict__ uvp,
         const float* __restrict__ prevv, float* __restrict__ cst)
{
    extern __shared__ char smem[];
    uint32_t sb = smem_u32(smem);
    float* aux = (float*)smem;                  // 128 floats
    float* sC = (float*)(smem + 1024);          // epilogue: 128 x SC_P floats
    int tid = threadIdx.x, lane = tid & 31, wid = tid >> 5;
    int m0 = blockIdx.x * 128, n0 = blockIdx.y * 128;

    if (EPI == E_BIASH && tid < 128) aux[tid] = bias[n0 + tid];
    if (EPI == E_LSTM && tid < 128) aux[tid] = uvp[n0 + tid];

    int warp_m = (wid & 3) * 32, warp_n = (wid >> 2) * 64;
    float acc[2][8][4];
#pragma unroll
    for (int i = 0; i < 2; i++)
#pragma unroll
        for (int j = 0; j < 8; j++)
#pragma unroll
            for (int k = 0; k < 4; k++) acc[i][j][k] = 0.f;

    const uint4 zz = make_uint4(0u, 0u, 0u, 0u);
    // ldmatrix lane addressing
    int a_r = lane & 15, a_k = (lane >> 4) * 16;
    int b_r = (lane & 7) | ((lane & 16) >> 1), b_k = ((lane >> 3) & 1) * 16;

#pragma unroll 1
    for (int kc = 0; kc < 4; kc++) {
        __syncthreads();
#pragma unroll
        for (int i = 0; i < 2; i++) {
            int linear = i * 256 + tid;
            int row = linear >> 3, q = linear & 7;
            // two row-phases per region: rows [0,64) then [64,128)
#pragma unroll
            for (int p = 0; p < 2; p++) {
                int rr = row + p * 64;
                uint32_t sw = swz(rr * 128 + q * 16);
                int gm = m0 + rr;
                uint4 va = zz;
                if (gm < M) va = *(const uint4*)(A + (size_t)gm * 256 + kc * 64 + q * 8);
                *(uint4*)(smem + SM_A + sw) = va;
                size_t gb = (size_t)(n0 + rr) * 256 + kc * 64 + q * 8;
                *(uint4*)(smem + SM_B + sw) = *(const uint4*)(B + gb);
            }
        }
        __syncthreads();

        // fp16 chunk accumulators (zeroed per chunk)
        uint32_t hacc[2][8][2];
#pragma unroll
        for (int i = 0; i < 2; i++)
#pragma unroll
            for (int j = 0; j < 8; j++) { hacc[i][j][0] = 0u; hacc[i][j][1] = 0u; }

#pragma unroll 1
        for (int ks = 0; ks < 4; ks++) {
            uint32_t a0[4], a1[4];
            LDSM4(a0, sb + SM_A + swz((warp_m + a_r) * 128 + ks * 32 + a_k));
            LDSM4(a1, sb + SM_A + swz((warp_m + 16 + a_r) * 128 + ks * 32 + a_k));
#pragma unroll
            for (int ng = 0; ng < 4; ng++) {
                uint32_t b[4];
                LDSM4(b, sb + SM_B + swz((warp_n + ng * 16 + b_r) * 128 + ks * 32 + b_k));
                MMA_F16A(hacc[0][2 * ng], a0, b[0], b[1]);
                MMA_F16A(hacc[0][2 * ng + 1], a0, b[2], b[3]);
                MMA_F16A(hacc[1][2 * ng], a1, b[0], b[1]);
                MMA_F16A(hacc[1][2 * ng + 1], a1, b[2], b[3]);
            }
        }

        // fp32 combine of chunk partials
#pragma unroll
        for (int i = 0; i < 2; i++)
#pragma unroll
            for (int j = 0; j < 8; j++) {
                float2 lo = __half22float2(*(__half2*)&hacc[i][j][0]);
                float2 hi = __half22float2(*(__half2*)&hacc[i][j][1]);
                acc[i][j][0] += lo.x;
                acc[i][j][1] += lo.y;
                acc[i][j][2] += hi.x;
                acc[i][j][3] += hi.y;
            }
    }

    // dump fragments to smem (pitch SC_P avoids bank conflicts on row-strided reads)
    __syncthreads();
    {
        int g = lane >> 2, ci = (lane & 3) * 2;
#pragma unroll
        for (int mt = 0; mt < 2; mt++)
#pragma unroll
            for (int nt = 0; nt < 8; nt++) {
                int row = warp_m + mt * 16 + g;
                int col = warp_n + nt * 8 + ci;
                sC[row * SC_P + col] = acc[mt][nt][0];
                sC[row * SC_P + col + 1] = acc[mt][nt][1];
                sC[(row + 8) * SC_P + col] = acc[mt][nt][2];
                sC[(row + 8) * SC_P + col + 1] = acc[mt][nt][3];
            }
    }
    __syncthreads();

    // epilogue: 2 threads per row, each handles 2 chunks of 32 cols
    int row = tid & 127, half = tid >> 7;
    int m = m0 + row;
    bool act = m < M;
    float pv = 0.f;
    if (EPI == E_LSTM && act) pv = prevv[m];

#pragma unroll 1
    for (int qq = 0; qq < 2; qq++) {
        int q = half * 2 + qq;
        if (!act) continue;
        float r[32];
#pragma unroll
        for (int i = 0; i < 32; i++) r[i] = sC[row * SC_P + q * 32 + i];

        if (EPI == E_STOREH || EPI == E_BIASH) {
            size_t ob = (size_t)m * ldc + n0 + q * 32;
#pragma unroll
            for (int b = 0; b < 4; b++) {
                uint4 uo;
                __half2* op = (__half2*)&uo;
#pragma unroll
                for (int j = 0; j < 4; j++) {
                    float v0 = r[8 * b + 2 * j], v1 = r[8 * b + 2 * j + 1];
                    if (EPI == E_BIASH) {
                        v0 += aux[q * 32 + 8 * b + 2 * j];
                        v1 += aux[q * 32 + 8 * b + 2 * j + 1];
                    }
                    op[j] = __floats2half2_rn(v0, v1);
                }
                *(uint4*)(Oh + ob + b * 8) = uo;
            }
        } else {  // E_LSTM
            float g0v[32];
            const uint4* gp4 = (const uint4*)(G0 + (size_t)m * ldc + n0 + q * 32);
#pragma unroll
            for (int i = 0; i < 4; i++) {
                uint4 t = gp4[i];
                __half2* hp = (__half2*)&t;
#pragma unroll
                for (int j = 0; j < 4; j++) {
                    float2 f = __half22float2(hp[j]);
                    g0v[8 * i + 2 * j] = f.x;
                    g0v[8 * i + 2 * j + 1] = f.y;
                }
            }
            int jb = (n0 + q * 32) >> 2;
            float c8[8];
            {
                float4 c0 = *(const float4*)(cst + (size_t)m * 256 + jb);
                float4 c1 = *(const float4*)(cst + (size_t)m * 256 + jb + 4);
                c8[0] = c0.x; c8[1] = c0.y; c8[2] = c0.z; c8[3] = c0.w;
                c8[4] = c1.x; c8[5] = c1.y; c8[6] = c1.z; c8[7] = c1.w;
            }
            __half hh[8];
#pragma unroll
            for (int f = 0; f < 8; f++) {
                int b = 4 * f;
                float ig = sigm(r[b + 0] + g0v[b + 0] + pv * aux[q * 32 + b + 0]);
                float fg = sigm(r[b + 1] + g0v[b + 1] + pv * aux[q * 32 + b + 1]);
                float gg = tanhf(r[b + 2] + g0v[b + 2] + pv * aux[q * 32 + b + 2]);
                float og = sigm(r[b + 3] + g0v[b + 3] + pv * aux[q * 32 + b + 3]);
                float cn = fg * c8[f] + ig * gg;
                c8[f] = cn;
                hh[f] = __float2half_rn(og * tanhf(cn));
            }
            {
                float4 c0 = make_float4(c8[0], c8[1], c8[2], c8[3]);
                float4 c1 = make_float4(c8[4], c8[5], c8[6], c8[7]);
                *(float4*)(cst + (size_t)m * 256 + jb) = c0;
                *(float4*)(cst + (size_t)m * 256 + jb + 4) = c1;
            }
            uint4 uo;
            __half2* op = (__half2*)&uo;
            op[0] = __halves2half2(hh[0], hh[1]);
            op[1] = __halves2half2(hh[2], hh[3]);
            op[2] = __halves2half2(hh[4], hh[5]);
            op[3] = __halves2half2(hh[6], hh[7]);
            *(uint4*)(Oh + (size_t)m * 256 + jb) = uo;
        }
    }
}

// ---------------- CSR build ----------------
__global__ void zero_i_k(int* p, int n) {
    int i = blockIdx.x * 256 + threadIdx.x;
    if (i < n) p[i] = 0;
}
__global__ void zero_f_k(float* p, int n) {
    int i = blockIdx.x * 256 + threadIdx.x;
    if (i < n) p[i] = 0.f;
}
__global__ void count_k(const int* __restrict__ dst, int* __restrict__ deg, int E) {
    int e = blockIdx.x * 256 + threadIdx.x;
    if (e < E) atomicAdd(&deg[dst[e]], 1);
}
__global__ void scan_k(const int* __restrict__ deg, int* __restrict__ off, int* __restrict__ cur, int n) {
    __shared__ int s[1024];
    int t = threadIdx.x;
    int per = (n + 1023) >> 10;
    int b = t * per;
    int e = min(b + per, n);
    int sum = 0;
    for (int i = b; i < e; i++) sum += deg[i];
    s[t] = sum;
    __syncthreads();
    for (int d = 1; d < 1024; d <<= 1) {
        int v = (t >= d) ? s[t - d] : 0;
        __syncthreads();
        s[t] += v;
        __syncthreads();
    }
    int run = s[t] - sum;
    for (int i = b; i < e; i++) { off[i] = run; cur[i] = run; run += deg[i]; }
    if (t == 1023) off[n] = s[1023];
}
__global__ void scatter_k(const int* __restrict__ dst, int* __restrict__ cur, int* __restrict__ eidx, int E) {
    int e = blockIdx.x * 256 + threadIdx.x;
    if (e < E) {
        int p = atomicAdd(&cur[dst[e]], 1);
        eidx[p] = e;
    }
}

// ---------------- weight prep (single fp16 term) ----------------
__global__ void wsT_k(const float* __restrict__ w, __half* __restrict__ oh) {
    int n = blockIdx.x, k = threadIdx.x;
    oh[n * 256 + k] = __float2half_rn(w[k * 256 + n]);
}
__global__ void mlpb_k(const float* __restrict__ mw, __half* __restrict__ oh) {
    int n = blockIdx.x, k = threadIdx.x;
    oh[n * 256 + k] = __float2half_rn(mw[n * 257 + 1 + k]);
}
__global__ void wperm_k(const float* __restrict__ w, __half* __restrict__ oh) {
    int pg = blockIdx.x, k = threadIdx.x;
    int row = (pg & 3) * 256 + (pg >> 2);
    oh[(size_t)pg * 256 + k] = __float2half_rn(w[(size_t)row * 256 + k]);
}
__global__ void uvec2_k(const float* __restrict__ wih, const float* __restrict__ mw,
                        const float* __restrict__ bih, const float* __restrict__ bhh,
                        float* __restrict__ up, float* __restrict__ bsp) {
    int pg = blockIdx.x * 256 + threadIdx.x;
    int row = (pg & 3) * 256 + (pg >> 2);
    float s = 0.f;
    for (int k = 0; k < 256; k++) s += wih[(size_t)row * 256 + k] * mw[k * 257];
    up[pg] = s;
    bsp[pg] = bih[row] + bhh[row];
}
__global__ void xhalf_k(const float* __restrict__ x, __half* __restrict__ o, int n) {
    int i = blockIdx.x * 256 + threadIdx.x;
    if (i < n) o[i] = __float2half_rn(x[i]);
}

// ---------------- GAT edge kernels ----------------
__device__ __forceinline__ float lreluf(float v) { return v > 0.f ? v : 0.2f * v; }
__device__ __forceinline__ float eluf(float v) { return v > 0.f ? v : expm1f(v); }

__global__ void edge_logits_k(const __half* __restrict__ xl, const __half* __restrict__ xr,
                              const int* __restrict__ src, const int* __restrict__ dst,
                              const float* __restrict__ att, float* __restrict__ elog, int E) {
    __shared__ float satt[HID];
    int tid = threadIdx.x;
    satt[tid] = att[tid];
    __syncthreads();
    int lane = tid & 31, w = tid >> 5;
    int e = blockIdx.x * 8 + w;
    if (e >= E) return;
    int s = src[e], d = dst[e];
    uint4 va = *(const uint4*)(xl + (size_t)s * HID + lane * 8);
    uint4 vb = *(const uint4*)(xr + (size_t)d * HID + lane * 8);
    __half2* ha = (__half2*)&va;
    __half2* hb = (__half2*)&vb;
    const float* at = satt + lane * 8;
    float p = 0.f;
#pragma unroll
    for (int j = 0; j < 4; j++) {
        float2 fa = __half22float2(ha[j]);
        float2 fb = __half22float2(hb[j]);
        p += at[2 * j] * lreluf(fa.x + fb.x);
        p += at[2 * j + 1] * lreluf(fa.y + fb.y);
    }
    p += __shfl_xor_sync(0xffffffffu, p, 1);
    p += __shfl_xor_sync(0xffffffffu, p, 2);
    p += __shfl_xor_sync(0xffffffffu, p, 4);
    if ((lane & 7) == 0) elog[(size_t)e * NH + (lane >> 3)] = expf(p);
}

__global__ void aggregate_k(const __half* __restrict__ xl, const float* __restrict__ elog,
                            const int* __restrict__ src,
                            const int* __restrict__ off, const int* __restrict__ eidx,
                            const float* __restrict__ bias,
                            __half* __restrict__ o, int N) {
    int tid = threadIdx.x;
    int lane = tid & 31, w = tid >> 5;
    int n = blockIdx.x * 8 + w;
    if (n >= N) return;
    int beg = off[n], end = off[n + 1];
    int h = lane >> 3;
    float den = 0.f;
    for (int j = beg; j < end; j++) den += elog[(size_t)eidx[j] * NH + h];
    float rin = 1.f / den;
    float a[8];
#pragma unroll
    for (int i = 0; i < 8; i++) a[i] = 0.f;
    for (int j = beg; j < end; j++) {
        int e = eidx[j];
        float wg = elog[(size_t)e * NH + h] * rin;
        uint4 vv = *(const uint4*)(xl + (size_t)src[e] * HID + lane * 8);
        __half2* hv = (__half2*)&vv;
#pragma unroll
        for (int i = 0; i < 4; i++) {
            float2 f = __half22float2(hv[i]);
            a[2 * i] += wg * f.x;
            a[2 * i + 1] += wg * f.y;
        }
    }
    const float* bb = bias + lane * 8;
    uint4 uo;
    __half2* op = (__half2*)&uo;
#pragma unroll
    for (int i = 0; i < 4; i++)
        op[i] = __floats2half2_rn(eluf(a[2 * i] + bb[2 * i]), eluf(a[2 * i + 1] + bb[2 * i + 1]));
    *(uint4*)(o + (size_t)n * HID + lane * 8) = uo;
}

// ---------------- decoder small kernels ----------------
__global__ void rowdot_h(const __half* __restrict__ hi,
                         const float* __restrict__ w, const float* __restrict__ b,
                         float* __restrict__ prev, float* __restrict__ outp, int step, int N) {
    int wid = blockIdx.x * 8 + (threadIdx.x >> 5);
    int lane = threadIdx.x & 31;
    if (wid >= N) return;
    size_t base = (size_t)wid * HID;
    float s = 0.f;
#pragma unroll
    for (int i = 0; i < 8; i++) {
        int k = lane + i * 32;
        s += __half2float(hi[base + k]) * w[k];
    }
    for (int d = 16; d; d >>= 1) s += __shfl_xor_sync(0xffffffffu, s, d);
    if (lane == 0) {
        float t = s + b[0];
        prev[wid] = t;
        if (outp) outp[(size_t)wid * TOUT + step] = t;
    }
}

// ---------------- launch ----------------
extern "C" void kernel_launch(void* const* d_in, const int* in_sizes, int n_in,
                              void* d_out, int out_size) {
    const float* x     = (const float*)d_in[0];
    const int*   ei    = (const int*)d_in[1];
    const float* w_src = (const float*)d_in[2];
    const float* w_dst = (const float*)d_in[3];
    const float* att   = (const float*)d_in[4];
    const float* gbias = (const float*)d_in[5];
    const float* mlp_w = (const float*)d_in[6];
    const float* mlp_b = (const float*)d_in[7];
    const float* wih   = (const float*)d_in[8];
    const float* whh   = (const float*)d_in[9];
    const float* bih   = (const float*)d_in[10];
    const float* bhh   = (const float*)d_in[11];
    const float* initw = (const float*)d_in[12];
    const float* initb = (const float*)d_in[13];
    const float* outw  = (const float*)d_in[14];
    const float* outb  = (const float*)d_in[15];
    float* out = (float*)d_out;

    int N = in_sizes[0] / HID;
    int E = in_sizes[1] / 2;

    float *elog, *cst, *prev, *up, *bsp;
    int *deg, *off, *cur, *eidx;
    __half *xl, *xr, *s0, *hA, *hB, *cs, *G0;
    __half *wg, *mb, *wihW, *whhW;
    cudaGetSymbolAddress((void**)&xl, g_xl);
    cudaGetSymbolAddress((void**)&xr, g_xr);
    cudaGetSymbolAddress((void**)&elog, g_elog);
    cudaGetSymbolAddress((void**)&G0, g_G0);
    cudaGetSymbolAddress((void**)&cst, g_c);
    cudaGetSymbolAddress((void**)&prev, g_prev);
    cudaGetSymbolAddress((void**)&up, g_up);
    cudaGetSymbolAddress((void**)&bsp, g_bsp);
    cudaGetSymbolAddress((void**)&deg, g_deg);
    cudaGetSymbolAddress((void**)&off, g_off);
    cudaGetSymbolAddress((void**)&cur, g_cur);
    cudaGetSymbolAddress((void**)&eidx, g_eidx);
    cudaGetSymbolAddress((void**)&s0, g_s0);
    cudaGetSymbolAddress((void**)&hA, g_hA);
    cudaGetSymbolAddress((void**)&hB, g_hB);
    cudaGetSymbolAddress((void**)&cs, g_cs);
    cudaGetSymbolAddress((void**)&wg, g_wg);
    cudaGetSymbolAddress((void**)&mb, g_mb);
    cudaGetSymbolAddress((void**)&wihW, g_wih);
    cudaGetSymbolAddress((void**)&whhW, g_whh);

    cudaFuncSetAttribute(gemm_mma<E_STOREH>, cudaFuncAttributeMaxDynamicSharedMemorySize, SM_TOTAL);
    cudaFuncSetAttribute(gemm_mma<E_BIASH>, cudaFuncAttributeMaxDynamicSharedMemorySize, SM_TOTAL);
    cudaFuncSetAttribute(gemm_mma<E_LSTM>, cudaFuncAttributeMaxDynamicSharedMemorySize, SM_TOTAL);

    int eb = (E + 255) / 256;
    int nb = (N + 255) / 256;

    // CSR by destination
    zero_i_k<<<nb, 256>>>(deg, N);
    count_k<<<eb, 256>>>(ei + E, deg, E);
    scan_k<<<1, 1024>>>(deg, off, cur, N);
    scatter_k<<<eb, 256>>>(ei + E, cur, eidx, E);

    // weight prep
    for (int l = 0; l < NL; l++) {
        wsT_k<<<256, 256>>>(w_src + (size_t)l * 65536, wg + (size_t)(2 * l) * 65536);
        wsT_k<<<256, 256>>>(w_dst + (size_t)l * 65536, wg + (size_t)(2 * l + 1) * 65536);
    }
    mlpb_k<<<256, 256>>>(mlp_w, mb);
    wperm_k<<<1024, 256>>>(wih, wihW);
    wperm_k<<<1024, 256>>>(whh, whhW);
    uvec2_k<<<4, 256>>>(wih, mlp_w, bih, bhh, up, bsp);
    xhalf_k<<<(N * HID + 255) / 256, 256>>>(x, s0, N * HID);
    zero_f_k<<<(N * HID + 255) / 256, 256>>>(cst, N * HID);

    int mg = (N + 127) / 128;
    int egrid = (E + 7) / 8;
    int ngrid = (N + 7) / 8;

    // GAT layers
    __half* sh = s0;
    for (int l = 0; l < NL; l++) {
        gemm_mma<E_STOREH><<<dim3(mg, 2), 256, SM_TOTAL>>>(
            sh, wg + (size_t)(2 * l) * 65536,
            N, HID, nullptr, xl, nullptr, nullptr, nullptr, nullptr);
        gemm_mma<E_STOREH><<<dim3(mg, 2), 256, SM_TOTAL>>>(
            sh, wg + (size_t)(2 * l + 1) * 65536,
            N, HID, nullptr, xr, nullptr, nullptr, nullptr, nullptr);
        edge_logits_k<<<egrid, 256>>>(xl, xr, ei, ei + E, att + l * HID, elog, E);
        __half* dof = (l == 0) ? s0 : hA;
        aggregate_k<<<ngrid, 256>>>(xl, elog, ei, off, eidx, gbias + l * HID, dof, N);
        sh = dof;
    }
    // sh == hA == h0 (fp16)

    // decoder precompute
    gemm_mma<E_BIASH><<<dim3(mg, 2), 256, SM_TOTAL>>>(
        hA, mb, N, HID, mlp_b, cs, nullptr, nullptr, nullptr, nullptr);
    gemm_mma<E_BIASH><<<dim3(mg, 8), 256, SM_TOTAL>>>(
        cs, wihW, N, 1024, bsp, G0, nullptr, nullptr, nullptr, nullptr);
    rowdot_h<<<ngrid, 256>>>(hA, initw, initb, prev, nullptr, 0, N);

    // recurrent steps: h ping-pongs A <-> B
    for (int s = 0; s < TOUT; s++) {
        __half* inh = (s & 1) ? hB : hA;
        __half* oh = (s & 1) ? hA : hB;
        gemm_mma<E_LSTM><<<dim3(mg, 8), 256, SM_TOTAL>>>(
            inh, whhW, N, 1024, nullptr, oh, G0, up, prev, cst);
        rowdot_h<<<ngrid, 256>>>(oh, outw, outb, prev, out, s, N);
    }
}

// round 17
// speedup vs baseline: 1.1007x; 1.1007x over previous
#include <cuda_runtime.h>
#include <cuda_fp16.h>
#include <math.h>
#include <stdint.h>

#define HID 256
#define NH 4
#define NL 2
#define TOUT 12
#define MAXN 24000
#define MAXE 400000

// ---------------- scratch (static device globals; no allocation) ----------------
__device__ __half g_xl[MAXN * HID];
__device__ __half g_xr[MAXN * HID];
__device__ int   g_deg[MAXN];
__device__ int   g_off[MAXN + 1];
__device__ int   g_cur[MAXN];
__device__ int   g_eidx[MAXE];
__device__ __half g_G0[(size_t)MAXN * 1024];
__device__ float g_c[MAXN * HID];
__device__ float g_prev[MAXN];
__device__ float g_up[1024];
__device__ float g_bsp[1024];

// fp16 activation buffers
__device__ __half g_s0[MAXN * HID];
__device__ __half g_hA[MAXN * HID];
__device__ __half g_hB[MAXN * HID];
__device__ __half g_cs[MAXN * HID];
// fp16 weights (single-term)
__device__ __half g_wg[4 * 256 * 256];
__device__ __half g_mb[256 * 256];
__device__ __half g_wih[1024 * 256];
__device__ __half g_whh[1024 * 256];

// ---------------- helpers ----------------
__device__ __forceinline__ uint32_t smem_u32(const void* p) {
    uint32_t a;
    asm("{ .reg .u64 t; cvta.to.shared.u64 t, %1; cvt.u32.u64 %0, t; }" : "=r"(a) : "l"(p));
    return a;
}
__device__ __forceinline__ uint32_t swz(uint32_t b) { return b ^ ((b >> 3) & 0x70); }
__device__ __forceinline__ float sigm(float x) { return 1.f / (1.f + expf(-x)); }

#define LDSM4(r, a) \
    asm volatile("ldmatrix.sync.aligned.m8n8.x4.shared.b16 {%0,%1,%2,%3}, [%4];" \
                 : "=r"((r)[0]), "=r"((r)[1]), "=r"((r)[2]), "=r"((r)[3]) : "r"(a))

#define MMA_F16(d, a, b0v, b1v) \
    asm volatile("mma.sync.aligned.m16n8k16.row.col.f32.f16.f16.f32 " \
                 "{%0,%1,%2,%3}, {%4,%5,%6,%7}, {%8,%9}, {%0,%1,%2,%3};" \
                 : "+f"((d)[0]), "+f"((d)[1]), "+f"((d)[2]), "+f"((d)[3]) \
                 : "r"((a)[0]), "r"((a)[1]), "r"((a)[2]), "r"((a)[3]), "r"(b0v), "r"(b1v))

// ---------------- HMMA GEMM: C[M,Nc] = A[M,256] @ W[Nc,256]^T (fp16 single-term) ----------------
// EXACT R13-proven structure (f32-acc MMA, synchronous loader). FROZEN — do not mutate.
#define SM_A  1024
#define SM_B  (1024 + 16384)
#define SC_P 129
#define SM_TOTAL (1024 + 128 * SC_P * 4)  // 67072 (mainloop needs 1024 + 32768)
enum { E_STOREH = 0, E_BIASH = 1, E_LSTM = 2 };

template <int EPI>
__global__ void __launch_bounds__(256, 2)
gemm_mma(const __half* __restrict__ A, const __half* __restrict__ B,
         int M, int ldc,
         const float* __restrict__ bias,
         __half* __restrict__ Oh,
         const __half* __restrict__ G0, const float* __restrict__ uvp,
         const float* __restrict__ prevv, float* __restrict__ cst)
{
    extern __shared__ char smem[];
    uint32_t sb = smem_u32(smem);
    float* aux = (float*)smem;                  // 128 floats
    float* sC = (float*)(smem + 1024);          // epilogue: 128 x SC_P floats
    int tid = threadIdx.x, lane = tid & 31, wid = tid >> 5;
    int m0 = blockIdx.x * 128, n0 = blockIdx.y * 128;

    if (EPI == E_BIASH && tid < 128) aux[tid] = bias[n0 + tid];
    if (EPI == E_LSTM && tid < 128) aux[tid] = uvp[n0 + tid];

    int warp_m = (wid & 3) * 32, warp_n = (wid >> 2) * 64;
    float acc[2][8][4];
#pragma unroll
    for (int i = 0; i < 2; i++)
#pragma unroll
        for (int j = 0; j < 8; j++)
#pragma unroll
            for (int k = 0; k < 4; k++) acc[i][j][k] = 0.f;

    const uint4 zz = make_uint4(0u, 0u, 0u, 0u);
    // ldmatrix lane addressing
    int a_r = lane & 15, a_k = (lane >> 4) * 16;
    int b_r = (lane & 7) | ((lane & 16) >> 1), b_k = ((lane >> 3) & 1) * 16;

#pragma unroll 1
    for (int kc = 0; kc < 4; kc++) {
        __syncthreads();
#pragma unroll
        for (int i = 0; i < 2; i++) {
            int linear = i * 256 + tid;
            int row = linear >> 3, q = linear & 7;
            // two row-phases per region: rows [0,64) then [64,128)
#pragma unroll
            for (int p = 0; p < 2; p++) {
                int rr = row + p * 64;
                uint32_t sw = swz(rr * 128 + q * 16);
                int gm = m0 + rr;
                uint4 va = zz;
                if (gm < M) va = *(const uint4*)(A + (size_t)gm * 256 + kc * 64 + q * 8);
                *(uint4*)(smem + SM_A + sw) = va;
                size_t gb = (size_t)(n0 + rr) * 256 + kc * 64 + q * 8;
                *(uint4*)(smem + SM_B + sw) = *(const uint4*)(B + gb);
            }
        }
        __syncthreads();
#pragma unroll 1
        for (int ks = 0; ks < 4; ks++) {
            uint32_t a0[4], a1[4];
            LDSM4(a0, sb + SM_A + swz((warp_m + a_r) * 128 + ks * 32 + a_k));
            LDSM4(a1, sb + SM_A + swz((warp_m + 16 + a_r) * 128 + ks * 32 + a_k));
#pragma unroll
            for (int ng = 0; ng < 4; ng++) {
                uint32_t b[4];
                LDSM4(b, sb + SM_B + swz((warp_n + ng * 16 + b_r) * 128 + ks * 32 + b_k));
                MMA_F16(acc[0][2 * ng], a0, b[0], b[1]);
                MMA_F16(acc[0][2 * ng + 1], a0, b[2], b[3]);
                MMA_F16(acc[1][2 * ng], a1, b[0], b[1]);
                MMA_F16(acc[1][2 * ng + 1], a1, b[2], b[3]);
            }
        }
    }

    // dump fragments to smem (pitch SC_P avoids bank conflicts on row-strided reads)
    __syncthreads();
    {
        int g = lane >> 2, ci = (lane & 3) * 2;
#pragma unroll
        for (int mt = 0; mt < 2; mt++)
#pragma unroll
            for (int nt = 0; nt < 8; nt++) {
                int row = warp_m + mt * 16 + g;
                int col = warp_n + nt * 8 + ci;
                sC[row * SC_P + col] = acc[mt][nt][0];
                sC[row * SC_P + col + 1] = acc[mt][nt][1];
                sC[(row + 8) * SC_P + col] = acc[mt][nt][2];
                sC[(row + 8) * SC_P + col + 1] = acc[mt][nt][3];
            }
    }
    __syncthreads();

    // epilogue: 2 threads per row, each handles 2 chunks of 32 cols
    int row = tid & 127, half = tid >> 7;
    int m = m0 + row;
    bool act = m < M;
    float pv = 0.f;
    if (EPI == E_LSTM && act) pv = prevv[m];

#pragma unroll 1
    for (int qq = 0; qq < 2; qq++) {
        int q = half * 2 + qq;
        if (!act) continue;
        float r[32];
#pragma unroll
        for (int i = 0; i < 32; i++) r[i] = sC[row * SC_P + q * 32 + i];

        if (EPI == E_STOREH || EPI == E_BIASH) {
            size_t ob = (size_t)m * ldc + n0 + q * 32;
#pragma unroll
            for (int b = 0; b < 4; b++) {
                uint4 uo;
                __half2* op = (__half2*)&uo;
#pragma unroll
                for (int j = 0; j < 4; j++) {
                    float v0 = r[8 * b + 2 * j], v1 = r[8 * b + 2 * j + 1];
                    if (EPI == E_BIASH) {
                        v0 += aux[q * 32 + 8 * b + 2 * j];
                        v1 += aux[q * 32 + 8 * b + 2 * j + 1];
                    }
                    op[j] = __floats2half2_rn(v0, v1);
                }
                *(uint4*)(Oh + ob + b * 8) = uo;
            }
        } else {  // E_LSTM
            float g0v[32];
            const uint4* gp4 = (const uint4*)(G0 + (size_t)m * ldc + n0 + q * 32);
#pragma unroll
            for (int i = 0; i < 4; i++) {
                uint4 t = gp4[i];
                __half2* hp = (__half2*)&t;
#pragma unroll
                for (int j = 0; j < 4; j++) {
                    float2 f = __half22float2(hp[j]);
                    g0v[8 * i + 2 * j] = f.x;
                    g0v[8 * i + 2 * j + 1] = f.y;
                }
            }
            int jb = (n0 + q * 32) >> 2;
            float c8[8];
            {
                float4 c0 = *(const float4*)(cst + (size_t)m * 256 + jb);
                float4 c1 = *(const float4*)(cst + (size_t)m * 256 + jb + 4);
                c8[0] = c0.x; c8[1] = c0.y; c8[2] = c0.z; c8[3] = c0.w;
                c8[4] = c1.x; c8[5] = c1.y; c8[6] = c1.z; c8[7] = c1.w;
            }
            __half hh[8];
#pragma unroll
            for (int f = 0; f < 8; f++) {
                int b = 4 * f;
                float ig = sigm(r[b + 0] + g0v[b + 0] + pv * aux[q * 32 + b + 0]);
                float fg = sigm(r[b + 1] + g0v[b + 1] + pv * aux[q * 32 + b + 1]);
                float gg = tanhf(r[b + 2] + g0v[b + 2] + pv * aux[q * 32 + b + 2]);
                float og = sigm(r[b + 3] + g0v[b + 3] + pv * aux[q * 32 + b + 3]);
                float cn = fg * c8[f] + ig * gg;
                c8[f] = cn;
                hh[f] = __float2half_rn(og * tanhf(cn));
            }
            {
                float4 c0 = make_float4(c8[0], c8[1], c8[2], c8[3]);
                float4 c1 = make_float4(c8[4], c8[5], c8[6], c8[7]);
                *(float4*)(cst + (size_t)m * 256 + jb) = c0;
                *(float4*)(cst + (size_t)m * 256 + jb + 4) = c1;
            }
            uint4 uo;
            __half2* op = (__half2*)&uo;
            op[0] = __halves2half2(hh[0], hh[1]);
            op[1] = __halves2half2(hh[2], hh[3]);
            op[2] = __halves2half2(hh[4], hh[5]);
            op[3] = __halves2half2(hh[6], hh[7]);
            *(uint4*)(Oh + (size_t)m * 256 + jb) = uo;
        }
    }
}

// ---------------- CSR build ----------------
__global__ void zero_i_k(int* p, int n) {
    int i = blockIdx.x * 256 + threadIdx.x;
    if (i < n) p[i] = 0;
}
__global__ void zero_f_k(float* p, int n) {
    int i = blockIdx.x * 256 + threadIdx.x;
    if (i < n) p[i] = 0.f;
}
__global__ void count_k(const int* __restrict__ dst, int* __restrict__ deg, int E) {
    int e = blockIdx.x * 256 + threadIdx.x;
    if (e < E) atomicAdd(&deg[dst[e]], 1);
}
__global__ void scan_k(const int* __restrict__ deg, int* __restrict__ off, int* __restrict__ cur, int n) {
    __shared__ int s[1024];
    int t = threadIdx.x;
    int per = (n + 1023) >> 10;
    int b = t * per;
    int e = min(b + per, n);
    int sum = 0;
    for (int i = b; i < e; i++) sum += deg[i];
    s[t] = sum;
    __syncthreads();
    for (int d = 1; d < 1024; d <<= 1) {
        int v = (t >= d) ? s[t - d] : 0;
        __syncthreads();
        s[t] += v;
        __syncthreads();
    }
    int run = s[t] - sum;
    for (int i = b; i < e; i++) { off[i] = run; cur[i] = run; run += deg[i]; }
    if (t == 1023) off[n] = s[1023];
}
__global__ void scatter_k(const int* __restrict__ dst, int* __restrict__ cur, int* __restrict__ eidx, int E) {
    int e = blockIdx.x * 256 + threadIdx.x;
    if (e < E) {
        int p = atomicAdd(&cur[dst[e]], 1);
        eidx[p] = e;
    }
}

// ---------------- weight prep (single fp16 term) ----------------
__global__ void wsT_k(const float* __restrict__ w, __half* __restrict__ oh) {
    int n = blockIdx.x, k = threadIdx.x;
    oh[n * 256 + k] = __float2half_rn(w[k * 256 + n]);
}
__global__ void mlpb_k(const float* __restrict__ mw, __half* __restrict__ oh) {
    int n = blockIdx.x, k = threadIdx.x;
    oh[n * 256 + k] = __float2half_rn(mw[n * 257 + 1 + k]);
}
__global__ void wperm_k(const float* __restrict__ w, __half* __restrict__ oh) {
    int pg = blockIdx.x, k = threadIdx.x;
    int row = (pg & 3) * 256 + (pg >> 2);
    oh[(size_t)pg * 256 + k] = __float2half_rn(w[(size_t)row * 256 + k]);
}
__global__ void uvec2_k(const float* __restrict__ wih, const float* __restrict__ mw,
                        const float* __restrict__ bih, const float* __restrict__ bhh,
                        float* __restrict__ up, float* __restrict__ bsp) {
    int pg = blockIdx.x * 256 + threadIdx.x;
    int row = (pg & 3) * 256 + (pg >> 2);
    float s = 0.f;
    for (int k = 0; k < 256; k++) s += wih[(size_t)row * 256 + k] * mw[k * 257];
    up[pg] = s;
    bsp[pg] = bih[row] + bhh[row];
}
__global__ void xhalf_k(const float* __restrict__ x, __half* __restrict__ o, int n) {
    int i = blockIdx.x * 256 + threadIdx.x;
    if (i < n) o[i] = __float2half_rn(x[i]);
}

// ---------------- fused GAT edge kernel ----------------
// One pass per destination node: logit + exp + denominator + weighted sum from a
// single load of each xl[src] row. out = (sum_e ex_e * xl_e) / (sum_e ex_e).
__device__ __forceinline__ float lreluf(float v) { return v > 0.f ? v : 0.2f * v; }
__device__ __forceinline__ float eluf(float v) { return v > 0.f ? v : expm1f(v); }

__global__ void gat_fused_k(const __half* __restrict__ xl, const __half* __restrict__ xr,
                            const int* __restrict__ src,
                            const int* __restrict__ off, const int* __restrict__ eidx,
                            const float* __restrict__ att, const float* __restrict__ bias,
                            __half* __restrict__ o, int N) {
    __shared__ float satt[HID];
    int tid = threadIdx.x;
    satt[tid] = att[tid];
    __syncthreads();
    int lane = tid & 31, w = tid >> 5;
    int n = blockIdx.x * 8 + w;
    if (n >= N) return;

    // xr row: 8 dims per lane (lane covers dims [lane*8, lane*8+8), head = lane>>3)
    float xrv[8];
    {
        uint4 vr = *(const uint4*)(xr + (size_t)n * HID + lane * 8);
        __half2* hr = (__half2*)&vr;
#pragma unroll
        for (int i = 0; i < 4; i++) {
            float2 f = __half22float2(hr[i]);
            xrv[2 * i] = f.x;
            xrv[2 * i + 1] = f.y;
        }
    }
    const float* at = satt + lane * 8;
    int beg = off[n], end = off[n + 1];
    float den = 0.f;
    float a[8];
#pragma unroll
    for (int i = 0; i < 8; i++) a[i] = 0.f;

    for (int j = beg; j < end; j++) {
        int e = eidx[j];
        uint4 vv = *(const uint4*)(xl + (size_t)src[e] * HID + lane * 8);
        __half2* hv = (__half2*)&vv;
        float xv[8];
#pragma unroll
        for (int i = 0; i < 4; i++) {
            float2 f = __half22float2(hv[i]);
            xv[2 * i] = f.x;
            xv[2 * i + 1] = f.y;
        }
        float p = 0.f;
#pragma unroll
        for (int i = 0; i < 8; i++) p += at[i] * lreluf(xv[i] + xrv[i]);
        // reduce across the 8-lane head group
        p += __shfl_xor_sync(0xffffffffu, p, 1);
        p += __shfl_xor_sync(0xffffffffu, p, 2);
        p += __shfl_xor_sync(0xffffffffu, p, 4);
        float ex = expf(p);
        den += ex;
#pragma unroll
        for (int i = 0; i < 8; i++) a[i] += ex * xv[i];
    }
    float rin = 1.f / den;
    const float* bb = bias + lane * 8;
    uint4 uo;
    __half2* op = (__half2*)&uo;
#pragma unroll
    for (int i = 0; i < 4; i++)
        op[i] = __floats2half2_rn(eluf(a[2 * i] * rin + bb[2 * i]),
                                  eluf(a[2 * i + 1] * rin + bb[2 * i + 1]));
    *(uint4*)(o + (size_t)n * HID + lane * 8) = uo;
}

// ---------------- decoder small kernels ----------------
__global__ void rowdot_h(const __half* __restrict__ hi,
                         const float* __restrict__ w, const float* __restrict__ b,
                         float* __restrict__ prev, float* __restrict__ outp, int step, int N) {
    int wid = blockIdx.x * 8 + (threadIdx.x >> 5);
    int lane = threadIdx.x & 31;
    if (wid >= N) return;
    size_t base = (size_t)wid * HID;
    float s = 0.f;
#pragma unroll
    for (int i = 0; i < 8; i++) {
        int k = lane + i * 32;
        s += __half2float(hi[base + k]) * w[k];
    }
    for (int d = 16; d; d >>= 1) s += __shfl_xor_sync(0xffffffffu, s, d);
    if (lane == 0) {
        float t = s + b[0];
        prev[wid] = t;
        if (outp) outp[(size_t)wid * TOUT + step] = t;
    }
}

// ---------------- launch ----------------
extern "C" void kernel_launch(void* const* d_in, const int* in_sizes, int n_in,
                              void* d_out, int out_size) {
    const float* x     = (const float*)d_in[0];
    const int*   ei    = (const int*)d_in[1];
    const float* w_src = (const float*)d_in[2];
    const float* w_dst = (const float*)d_in[3];
    const float* att   = (const float*)d_in[4];
    const float* gbias = (const float*)d_in[5];
    const float* mlp_w = (const float*)d_in[6];
    const float* mlp_b = (const float*)d_in[7];
    const float* wih   = (const float*)d_in[8];
    const float* whh   = (const float*)d_in[9];
    const float* bih   = (const float*)d_in[10];
    const float* bhh   = (const float*)d_in[11];
    const float* initw = (const float*)d_in[12];
    const float* initb = (const float*)d_in[13];
    const float* outw  = (const float*)d_in[14];
    const float* outb  = (const float*)d_in[15];
    float* out = (float*)d_out;

    int N = in_sizes[0] / HID;
    int E = in_sizes[1] / 2;

    float *cst, *prev, *up, *bsp;
    int *deg, *off, *cur, *eidx;
    __half *xl, *xr, *s0, *hA, *hB, *cs, *G0;
    __half *wg, *mb, *wihW, *whhW;
    cudaGetSymbolAddress((void**)&xl, g_xl);
    cudaGetSymbolAddress((void**)&xr, g_xr);
    cudaGetSymbolAddress((void**)&G0, g_G0);
    cudaGetSymbolAddress((void**)&cst, g_c);
    cudaGetSymbolAddress((void**)&prev, g_prev);
    cudaGetSymbolAddress((void**)&up, g_up);
    cudaGetSymbolAddress((void**)&bsp, g_bsp);
    cudaGetSymbolAddress((void**)&deg, g_deg);
    cudaGetSymbolAddress((void**)&off, g_off);
    cudaGetSymbolAddress((void**)&cur, g_cur);
    cudaGetSymbolAddress((void**)&eidx, g_eidx);
    cudaGetSymbolAddress((void**)&s0, g_s0);
    cudaGetSymbolAddress((void**)&hA, g_hA);
    cudaGetSymbolAddress((void**)&hB, g_hB);
    cudaGetSymbolAddress((void**)&cs, g_cs);
    cudaGetSymbolAddress((void**)&wg, g_wg);
    cudaGetSymbolAddress((void**)&mb, g_mb);
    cudaGetSymbolAddress((void**)&wihW, g_wih);
    cudaGetSymbolAddress((void**)&whhW, g_whh);

    cudaFuncSetAttribute(gemm_mma<E_STOREH>, cudaFuncAttributeMaxDynamicSharedMemorySize, SM_TOTAL);
    cudaFuncSetAttribute(gemm_mma<E_BIASH>, cudaFuncAttributeMaxDynamicSharedMemorySize, SM_TOTAL);
    cudaFuncSetAttribute(gemm_mma<E_LSTM>, cudaFuncAttributeMaxDynamicSharedMemorySize, SM_TOTAL);

    int eb = (E + 255) / 256;
    int nb = (N + 255) / 256;

    // CSR by destination
    zero_i_k<<<nb, 256>>>(deg, N);
    count_k<<<eb, 256>>>(ei + E, deg, E);
    scan_k<<<1, 1024>>>(deg, off, cur, N);
    scatter_k<<<eb, 256>>>(ei + E, cur, eidx, E);

    // weight prep
    for (int l = 0; l < NL; l++) {
        wsT_k<<<256, 256>>>(w_src + (size_t)l * 65536, wg + (size_t)(2 * l) * 65536);
        wsT_k<<<256, 256>>>(w_dst + (size_t)l * 65536, wg + (size_t)(2 * l + 1) * 65536);
    }
    mlpb_k<<<256, 256>>>(mlp_w, mb);
    wperm_k<<<1024, 256>>>(wih, wihW);
    wperm_k<<<1024, 256>>>(whh, whhW);
    uvec2_k<<<4, 256>>>(wih, mlp_w, bih, bhh, up, bsp);
    xhalf_k<<<(N * HID + 255) / 256, 256>>>(x, s0, N * HID);
    zero_f_k<<<(N * HID + 255) / 256, 256>>>(cst, N * HID);

    int mg = (N + 127) / 128;
    int ngrid = (N + 7) / 8;

    // GAT layers (fused edge softmax + aggregation)
    __half* sh = s0;
    for (int l = 0; l < NL; l++) {
        gemm_mma<E_STOREH><<<dim3(mg, 2), 256, SM_TOTAL>>>(
            sh, wg + (size_t)(2 * l) * 65536,
            N, HID, nullptr, xl, nullptr, nullptr, nullptr, nullptr);
        gemm_mma<E_STOREH><<<dim3(mg, 2), 256, SM_TOTAL>>>(
            sh, wg + (size_t)(2 * l + 1) * 65536,
            N, HID, nullptr, xr, nullptr, nullptr, nullptr, nullptr);
        __half* dof = (l == 0) ? s0 : hA;
        gat_fused_k<<<ngrid, 256>>>(xl, xr, ei, off, eidx, att + l * HID,
                                    gbias + l * HID, dof, N);
        sh = dof;
    }
    // sh == hA == h0 (fp16)

    // decoder precompute
    gemm_mma<E_BIASH><<<dim3(mg, 2), 256, SM_TOTAL>>>(
        hA, mb, N, HID, mlp_b, cs, nullptr, nullptr, nullptr, nullptr);
    gemm_mma<E_BIASH><<<dim3(mg, 8), 256, SM_TOTAL>>>(
        cs, wihW, N, 1024, bsp, G0, nullptr, nullptr, nullptr, nullptr);
    rowdot_h<<<ngrid, 256>>>(hA, initw, initb, prev, nullptr, 0, N);

    // recurrent steps: h ping-pongs A <-> B
    for (int s = 0; s < TOUT; s++) {
        __half* inh = (s & 1) ? hB : hA;
        __half* oh = (s & 1) ? hA : hB;
        gemm_mma<E_LSTM><<<dim3(mg, 8), 256, SM_TOTAL>>>(
            inh, whhW, N, 1024, nullptr, oh, G0, up, prev, cst);
        rowdot_h<<<ngrid, 256>>>(oh, outw, outb, prev, out, s, N);
    }
}